// round 12
// baseline (speedup 1.0000x reference)
#include <cuda_runtime.h>
#include <cuda_fp16.h>
#include <cstdint>

#define NN  50000
#define EE  800000
#define FIN 128
#define KK  32
#define CAP 64    // per-node bucket capacity (max in-degree ~42 w.h.p.)
#define AS  136   // smem tile stride in fp16 elems (128 + 8 pad)

#define EQ      (EE / 4)                    // 200000 edges per strip
#define SCAT_B  ((EQ + 255) / 256)          // 782 blocks, 4 edges/thread
#define XS_B    ((NN + 7) / 8)              // 6250 blocks
#define WP_B    64

typedef unsigned long long u64;

// ---------------- device scratch (no allocations allowed) ----------------
__device__ __half g_xs[(size_t)NN * FIN];   // dense MaxK features, fp16
__device__ __half g_agg[(size_t)NN * FIN];  // normalized neighbor agg, fp16
__device__ int   g_cur[NN];                 // fill count == in-degree; zeroed by agg
__device__ int   g_csr[(size_t)NN * CAP];   // bucketed src ids
// Pre-built fp16 MMA B fragments: [ph][kstep(8)][wcol(2)][lane(32)][16]
__device__ uint32_t g_bf[2][8][2][32][16];

// ---------------- PTX helpers (baseline sm_80-class only) ----------------
__device__ __forceinline__ uint32_t smem_u32(const void* p) {
    uint32_t a;
    asm("{ .reg .u64 t; cvta.to.shared.u64 t, %1; cvt.u32.u64 %0, t; }" : "=r"(a) : "l"(p));
    return a;
}
__device__ __forceinline__ void ldm_x4(uint32_t* r, uint32_t addr) {
    asm volatile("ldmatrix.sync.aligned.m8n8.x4.shared.b16 {%0,%1,%2,%3}, [%4];"
                 : "=r"(r[0]), "=r"(r[1]), "=r"(r[2]), "=r"(r[3]) : "r"(addr));
}
__device__ __forceinline__ void mma_fp16(float* c, const uint32_t* a, uint32_t b0, uint32_t b1) {
    asm volatile(
        "mma.sync.aligned.m16n8k16.row.col.f32.f16.f16.f32 "
        "{%0,%1,%2,%3}, {%4,%5,%6,%7}, {%8,%9}, {%0,%1,%2,%3};"
        : "+f"(c[0]), "+f"(c[1]), "+f"(c[2]), "+f"(c[3])
        : "r"(a[0]), "r"(a[1]), "r"(a[2]), "r"(a[3]), "r"(b0), "r"(b1));
}
__device__ __forceinline__ uint32_t ldm_addr(uint32_t base, int row, int col, int lane) {
    int r = row + (lane & 15);
    int c = col + ((lane >> 4) << 3);
    return base + (uint32_t)((r * AS + c) * 2);
}
__device__ __forceinline__ void cp_async16(uint32_t smem_addr, const void* gptr, int src_bytes) {
    asm volatile("cp.async.cg.shared.global [%0], [%1], 16, %2;"
                 :: "r"(smem_addr), "l"(gptr), "r"(src_bytes) : "memory");
}
#define CP_ASYNC_COMMIT() asm volatile("cp.async.commit_group;" ::: "memory")
#define CP_ASYNC_WAIT0()  asm volatile("cp.async.wait_group 0;" ::: "memory")

// ---------------- fused prep: scatter + xs + wprep ----------------
__global__ void prep_kernel(const int* __restrict__ src, const int* __restrict__ dst,
                            const float* __restrict__ tv, const int* __restrict__ ti,
                            const float* __restrict__ Ws, const float* __restrict__ Wn) {
    __shared__ __half srow[8][128];   // one dense row per warp
    int b = blockIdx.x;

    if (b < SCAT_B) {
        // ---- bucket scatter, 4 independent edges per thread (MLP) ----
        int e0 = b * 256 + threadIdx.x;
        if (e0 < EQ) {
            int d0 = dst[e0],          s0 = src[e0];
            int d1 = dst[e0 + EQ],     s1 = src[e0 + EQ];
            int d2 = dst[e0 + 2 * EQ], s2 = src[e0 + 2 * EQ];
            int d3 = dst[e0 + 3 * EQ], s3 = src[e0 + 3 * EQ];
            int p0 = atomicAdd(&g_cur[d0], 1);
            int p1 = atomicAdd(&g_cur[d1], 1);
            int p2 = atomicAdd(&g_cur[d2], 1);
            int p3 = atomicAdd(&g_cur[d3], 1);
            if (p0 < CAP) g_csr[(size_t)d0 * CAP + p0] = s0;
            if (p1 < CAP) g_csr[(size_t)d1 * CAP + p1] = s1;
            if (p2 < CAP) g_csr[(size_t)d2 * CAP + p2] = s2;
            if (p3 < CAP) g_csr[(size_t)d3 * CAP + p3] = s3;
        }
        return;
    }
    b -= SCAT_B;

    if (b < XS_B) {
        // ---- dense x_sparse rows (fp16), last-wins via match_any ----
        int w = threadIdx.x >> 5, lane = threadIdx.x & 31;
        int row = b * 8 + w;
        if (row >= NN) return;
        int   idx = ti[row * KK + lane];
        float val = tv[row * KK + lane];
        // last-wins: for equal indices the highest lane (= highest k) wins
        unsigned mask = __match_any_sync(0xffffffffu, idx);
        bool winner = (lane == 31 - __clz(mask));
        ((uint32_t*)srow[w])[lane]      = 0u;
        ((uint32_t*)srow[w])[lane + 32] = 0u;
        __syncwarp();
        if (winner) srow[w][idx] = __float2half_rn(val);
        __syncwarp();
        uint2 pk = ((const uint2*)srow[w])[lane];
        *(uint2*)&g_xs[(size_t)row * FIN + lane * 4] = pk;
        return;
    }
    b -= XS_B;

    // ---- wprep: fp16 MMA B fragments from W (row-major [k][n]) ----
    {
        int idx = b * 256 + threadIdx.x;   // 0..16383
        int j    = idx & 15;
        int lane = (idx >> 4) & 31;
        int wc   = (idx >> 9) & 1;
        int ks   = (idx >> 10) & 7;
        int ph   = (idx >> 13) & 1;
        int nf = j >> 1, r = j & 1;
        int k = ks * 16 + (lane & 3) * 2 + r * 8;
        int n = wc * 64 + nf * 8 + (lane >> 2);
        const float* W = ph ? Wn : Ws;
        __half2 outp = __floats2half2_rn(W[k * 128 + n], W[(k + 1) * 128 + n]);
        ((uint32_t*)g_bf)[idx] = *(uint32_t*)&outp;
    }
}

// One warp per dst node; 2-edge unrolled inner loop, dual accumulators.
// Clears g_cur for the next replay (graph-deterministic).
__global__ void agg_kernel() {
    int gw = (blockIdx.x * blockDim.x + threadIdx.x) >> 5;
    int lane = threadIdx.x & 31;
    if (gw >= NN) return;
    int deg = min(g_cur[gw], CAP);
    const int* bucket = &g_csr[(size_t)gw * CAP];
    float4 accA = make_float4(0.f, 0.f, 0.f, 0.f);
    float4 accB = make_float4(0.f, 0.f, 0.f, 0.f);
    for (int chunk = 0; chunk < deg; chunk += 32) {
        int i = chunk + lane;
        int s = (i < deg) ? bucket[i] : 0;
        int m = min(32, deg - chunk);
        int j = 0;
        for (; j + 1 < m; j += 2) {
            int ss0 = __shfl_sync(0xffffffffu, s, j);
            int ss1 = __shfl_sync(0xffffffffu, s, j + 1);
            uint2 pk0 = *(const uint2*)&g_xs[(size_t)ss0 * FIN + lane * 4];
            uint2 pk1 = *(const uint2*)&g_xs[(size_t)ss1 * FIN + lane * 4];
            float2 a01 = __half22float2(*(__half2*)&pk0.x);
            float2 a23 = __half22float2(*(__half2*)&pk0.y);
            float2 b01 = __half22float2(*(__half2*)&pk1.x);
            float2 b23 = __half22float2(*(__half2*)&pk1.y);
            accA.x += a01.x; accA.y += a01.y; accA.z += a23.x; accA.w += a23.y;
            accB.x += b01.x; accB.y += b01.y; accB.z += b23.x; accB.w += b23.y;
        }
        if (j < m) {
            int ss0 = __shfl_sync(0xffffffffu, s, j);
            uint2 pk0 = *(const uint2*)&g_xs[(size_t)ss0 * FIN + lane * 4];
            float2 a01 = __half22float2(*(__half2*)&pk0.x);
            float2 a23 = __half22float2(*(__half2*)&pk0.y);
            accA.x += a01.x; accA.y += a01.y; accA.z += a23.x; accA.w += a23.y;
        }
    }
    float wgt = 1.0f / (float)max(deg, 1);
    __half2 h01 = __floats2half2_rn((accA.x + accB.x) * wgt, (accA.y + accB.y) * wgt);
    __half2 h23 = __floats2half2_rn((accA.z + accB.z) * wgt, (accA.w + accB.w) * wgt);
    uint2 pk = make_uint2(*(uint32_t*)&h01, *(uint32_t*)&h23);
    *(uint2*)&g_agg[(size_t)gw * FIN + lane * 4] = pk;
    __syncwarp();
    if (lane == 0) g_cur[gw] = 0;   // reset for next replay
}

// ---------------- single-pass fp16 HMMA GEMM (fused K=256) ----------------
// out = [feat | agg] @ [[W_self],[W_neigh]] + b
// Phase-1 (agg) tile prefetched via cp.async into a second buffer, hidden
// behind phase-0 MMAs.
#define SM_A0 0
#define SM_A1 (128 * AS * 2)
#define SM_TOTAL (2 * 128 * AS * 2)   // 69,632 bytes

__global__ void __launch_bounds__(256, 2) gemm_kernel(
    const float* __restrict__ feat,
    const float* __restrict__ bself,
    float* __restrict__ out)
{
    extern __shared__ char smem[];
    uint32_t sb = smem_u32(smem);
    const int t = threadIdx.x, w = t >> 5, lane = t & 31;
    const int rowBase = blockIdx.x * 128;
    const int wm = (w & 3) * 32, wc = w >> 2;

    float acc[2][8][4];
    #pragma unroll
    for (int mf = 0; mf < 2; mf++)
        #pragma unroll
        for (int nf = 0; nf < 8; nf++)
            #pragma unroll
            for (int e = 0; e < 4; e++) acc[mf][nf][e] = 0.f;

    const int fr = t >> 1, half = t & 1;
    const int gr = rowBase + fr;
    const bool valid = gr < NN;
    const int grc = valid ? gr : (NN - 1);   // clamped for cp.async address

    // ---- prefetch agg tile (phase 1) via cp.async, zero-fill OOB rows ----
    #pragma unroll
    for (int j = 0; j < 8; j++) {
        int c = half * 64 + j * 8;
        cp_async16(sb + SM_A1 + (uint32_t)((fr * AS + c) * 2),
                   &g_agg[(size_t)grc * FIN + c], valid ? 16 : 0);
    }
    CP_ASYNC_COMMIT();

    // ---- A fill phase 0: fp32 feat -> fp16 smem ----
    #pragma unroll 4
    for (int j = 0; j < 16; j++) {
        int c = half * 64 + j * 4;
        float4 v = valid ? *(const float4*)(feat + (size_t)gr * FIN + c)
                         : make_float4(0.f, 0.f, 0.f, 0.f);
        __half2 h01 = __floats2half2_rn(v.x, v.y);
        __half2 h23 = __floats2half2_rn(v.z, v.w);
        uint32_t o = (uint32_t)((fr * AS + c) * 2);
        *(__half2*)(smem + SM_A0 + o)     = h01;
        *(__half2*)(smem + SM_A0 + o + 4) = h23;
    }
    __syncthreads();

    #pragma unroll
    for (int ph = 0; ph < 2; ph++) {
        uint32_t base = sb + (ph ? SM_A1 : SM_A0);
        if (ph) {
            CP_ASYNC_WAIT0();
            __syncthreads();
        }
        // ---- MMA mainloop: 8 k-steps, double-buffered B fragments ----
        uint32_t bfr[2][16];
        {
            const uint4* hp = (const uint4*)&g_bf[ph][0][wc][lane][0];
            #pragma unroll
            for (int q = 0; q < 4; q++) *(uint4*)&bfr[0][q * 4] = hp[q];
        }
        #pragma unroll
        for (int ks = 0; ks < 8; ks++) {
            int cur = ks & 1, nxt = cur ^ 1;
            if (ks < 7) {
                const uint4* hp = (const uint4*)&g_bf[ph][ks + 1][wc][lane][0];
                #pragma unroll
                for (int q = 0; q < 4; q++) *(uint4*)&bfr[nxt][q * 4] = hp[q];
            }
            uint32_t afr[2][4];
            #pragma unroll
            for (int mf = 0; mf < 2; mf++)
                ldm_x4(afr[mf], ldm_addr(base, wm + mf * 16, ks * 16, lane));
            #pragma unroll
            for (int mf = 0; mf < 2; mf++)
                #pragma unroll
                for (int nf = 0; nf < 8; nf++)
                    mma_fp16(acc[mf][nf], afr[mf], bfr[cur][nf * 2], bfr[cur][nf * 2 + 1]);
        }
    }

    // ---- epilogue: +bias, store ----
    const int wn = wc * 64, cg = (lane & 3) * 2, rr = lane >> 2;
    #pragma unroll
    for (int mf = 0; mf < 2; mf++) {
        int r0 = rowBase + wm + mf * 16 + rr, r1 = r0 + 8;
        #pragma unroll
        for (int nf = 0; nf < 8; nf++) {
            int col = wn + nf * 8 + cg;
            float b0 = __ldg(bself + col), b1 = __ldg(bself + col + 1);
            if (r0 < NN)
                *(float2*)(out + (size_t)r0 * FIN + col) =
                    make_float2(acc[mf][nf][0] + b0, acc[mf][nf][1] + b1);
            if (r1 < NN)
                *(float2*)(out + (size_t)r1 * FIN + col) =
                    make_float2(acc[mf][nf][2] + b0, acc[mf][nf][3] + b1);
        }
    }
}

// ---------------- launch ----------------
extern "C" void kernel_launch(void* const* d_in, const int* in_sizes, int n_in,
                              void* d_out, int out_size) {
    const float *feat = nullptr, *topkv = nullptr, *Wself = nullptr,
                *bself = nullptr, *Wneigh = nullptr;
    const int *topki = nullptr, *src = nullptr, *dst = nullptr;

    for (int i = 0; i < n_in; i++) {
        int s = in_sizes[i];
        const void* p = d_in[i];
        if (s == NN * FIN)       feat = (const float*)p;
        else if (s == NN * KK) { if (!topkv) topkv = (const float*)p; else topki = (const int*)p; }
        else if (s == EE)      { if (!src)   src   = (const int*)p;   else dst   = (const int*)p; }
        else if (s == 128*128) { if (!Wself) Wself = (const float*)p; else Wneigh = (const float*)p; }
        else if (s == 128)       bself = (const float*)p;
    }
    float* out = (float*)d_out;

    static int inited = 0;
    if (!inited) {
        cudaFuncSetAttribute(gemm_kernel, cudaFuncAttributeMaxDynamicSharedMemorySize, SM_TOTAL);
        inited = 1;
    }

    prep_kernel<<<SCAT_B + XS_B + WP_B, 256>>>(src, dst, topkv, topki, Wself, Wneigh);
    agg_kernel<<<(NN + 7) / 8, 256>>>();
    gemm_kernel<<<(NN + 127) / 128, 256, SM_TOTAL>>>(feat, bself, out);
}

// round 13
// speedup vs baseline: 1.4198x; 1.4198x over previous
#include <cuda_runtime.h>
#include <cuda_fp16.h>
#include <cstdint>

#define NN  50000
#define EE  800000
#define FIN 128
#define KK  32
#define CAP 64    // per-node bucket capacity (max in-degree ~42 w.h.p.)
#define AS  136   // smem tile stride in fp16 elems (128 + 8 pad)

#define EHALF   (EE / 2)                    // 400000
#define SCAT_B  ((EHALF + 255) / 256)       // 1563 blocks, 2 edges/thread
#define XS_B    ((NN + 7) / 8)              // 6250 blocks
#define WP_B    64

typedef unsigned long long u64;

// ---------------- device scratch (no allocations allowed) ----------------
__device__ __half g_xs[(size_t)NN * FIN];   // dense MaxK features, fp16
__device__ __half g_agg[(size_t)NN * FIN];  // normalized neighbor agg, fp16
__device__ int   g_cur[NN];                 // fill count == in-degree; zeroed by agg
__device__ int   g_csr[(size_t)NN * CAP];   // bucketed src ids
// Pre-built fp16 MMA B fragments: [ph][kstep(8)][wcol(2)][lane(32)][16]
__device__ uint32_t g_bf[2][8][2][32][16];

// ---------------- PTX helpers (baseline sm_80-class only) ----------------
__device__ __forceinline__ uint32_t smem_u32(const void* p) {
    uint32_t a;
    asm("{ .reg .u64 t; cvta.to.shared.u64 t, %1; cvt.u32.u64 %0, t; }" : "=r"(a) : "l"(p));
    return a;
}
__device__ __forceinline__ void ldm_x4(uint32_t* r, uint32_t addr) {
    asm volatile("ldmatrix.sync.aligned.m8n8.x4.shared.b16 {%0,%1,%2,%3}, [%4];"
                 : "=r"(r[0]), "=r"(r[1]), "=r"(r[2]), "=r"(r[3]) : "r"(addr));
}
__device__ __forceinline__ void mma_fp16(float* c, const uint32_t* a, uint32_t b0, uint32_t b1) {
    asm volatile(
        "mma.sync.aligned.m16n8k16.row.col.f32.f16.f16.f32 "
        "{%0,%1,%2,%3}, {%4,%5,%6,%7}, {%8,%9}, {%0,%1,%2,%3};"
        : "+f"(c[0]), "+f"(c[1]), "+f"(c[2]), "+f"(c[3])
        : "r"(a[0]), "r"(a[1]), "r"(a[2]), "r"(a[3]), "r"(b0), "r"(b1));
}
__device__ __forceinline__ uint32_t ldm_addr(uint32_t base, int row, int col, int lane) {
    int r = row + (lane & 15);
    int c = col + ((lane >> 4) << 3);
    return base + (uint32_t)((r * AS + c) * 2);
}

// ---------------- fused prep: scatter + xs + wprep ----------------
__global__ void prep_kernel(const int* __restrict__ src, const int* __restrict__ dst,
                            const float* __restrict__ tv, const int* __restrict__ ti,
                            const float* __restrict__ Ws, const float* __restrict__ Wn) {
    __shared__ __half srow[8][128];   // one dense row per warp
    int b = blockIdx.x;

    if (b < SCAT_B) {
        // ---- bucket scatter, 2 independent edges per thread ----
        int e0 = b * 256 + threadIdx.x;
        int e1 = e0 + EHALF;
        if (e0 < EHALF) {
            int d0 = dst[e0], d1 = dst[e1];
            int s0 = src[e0], s1 = src[e1];
            int p0 = atomicAdd(&g_cur[d0], 1);
            int p1 = atomicAdd(&g_cur[d1], 1);
            if (p0 < CAP) g_csr[(size_t)d0 * CAP + p0] = s0;
            if (p1 < CAP) g_csr[(size_t)d1 * CAP + p1] = s1;
        }
        return;
    }
    b -= SCAT_B;

    if (b < XS_B) {
        // ---- dense x_sparse rows (fp16), last-wins via match_any ----
        int w = threadIdx.x >> 5, lane = threadIdx.x & 31;
        int row = b * 8 + w;
        if (row >= NN) return;
        int   idx = ti[row * KK + lane];
        float val = tv[row * KK + lane];
        // last-wins: for equal indices the highest lane (= highest k) wins
        unsigned mask = __match_any_sync(0xffffffffu, idx);
        bool winner = (lane == 31 - __clz(mask));
        ((uint32_t*)srow[w])[lane]      = 0u;
        ((uint32_t*)srow[w])[lane + 32] = 0u;
        __syncwarp();
        if (winner) srow[w][idx] = __float2half_rn(val);
        __syncwarp();
        uint2 pk = ((const uint2*)srow[w])[lane];
        *(uint2*)&g_xs[(size_t)row * FIN + lane * 4] = pk;
        return;
    }
    b -= XS_B;

    // ---- wprep: fp16 MMA B fragments from W (row-major [k][n]) ----
    {
        int idx = b * 256 + threadIdx.x;   // 0..16383
        int j    = idx & 15;
        int lane = (idx >> 4) & 31;
        int wc   = (idx >> 9) & 1;
        int ks   = (idx >> 10) & 7;
        int ph   = (idx >> 13) & 1;
        int nf = j >> 1, r = j & 1;
        int k = ks * 16 + (lane & 3) * 2 + r * 8;
        int n = wc * 64 + nf * 8 + (lane >> 2);
        const float* W = ph ? Wn : Ws;
        __half2 outp = __floats2half2_rn(W[k * 128 + n], W[(k + 1) * 128 + n]);
        ((uint32_t*)g_bf)[idx] = *(uint32_t*)&outp;
    }
}

// One warp per dst node; 2-edge unrolled inner loop, dual accumulators.
// Clears g_cur for the next replay (graph-deterministic).
__global__ void agg_kernel() {
    int gw = (blockIdx.x * blockDim.x + threadIdx.x) >> 5;
    int lane = threadIdx.x & 31;
    if (gw >= NN) return;
    int deg = min(g_cur[gw], CAP);
    const int* bucket = &g_csr[(size_t)gw * CAP];
    float4 accA = make_float4(0.f, 0.f, 0.f, 0.f);
    float4 accB = make_float4(0.f, 0.f, 0.f, 0.f);
    for (int chunk = 0; chunk < deg; chunk += 32) {
        int i = chunk + lane;
        int s = (i < deg) ? bucket[i] : 0;
        int m = min(32, deg - chunk);
        int j = 0;
        for (; j + 1 < m; j += 2) {
            int ss0 = __shfl_sync(0xffffffffu, s, j);
            int ss1 = __shfl_sync(0xffffffffu, s, j + 1);
            uint2 pk0 = *(const uint2*)&g_xs[(size_t)ss0 * FIN + lane * 4];
            uint2 pk1 = *(const uint2*)&g_xs[(size_t)ss1 * FIN + lane * 4];
            float2 a01 = __half22float2(*(__half2*)&pk0.x);
            float2 a23 = __half22float2(*(__half2*)&pk0.y);
            float2 b01 = __half22float2(*(__half2*)&pk1.x);
            float2 b23 = __half22float2(*(__half2*)&pk1.y);
            accA.x += a01.x; accA.y += a01.y; accA.z += a23.x; accA.w += a23.y;
            accB.x += b01.x; accB.y += b01.y; accB.z += b23.x; accB.w += b23.y;
        }
        if (j < m) {
            int ss0 = __shfl_sync(0xffffffffu, s, j);
            uint2 pk0 = *(const uint2*)&g_xs[(size_t)ss0 * FIN + lane * 4];
            float2 a01 = __half22float2(*(__half2*)&pk0.x);
            float2 a23 = __half22float2(*(__half2*)&pk0.y);
            accA.x += a01.x; accA.y += a01.y; accA.z += a23.x; accA.w += a23.y;
        }
    }
    float wgt = 1.0f / (float)max(deg, 1);
    __half2 h01 = __floats2half2_rn((accA.x + accB.x) * wgt, (accA.y + accB.y) * wgt);
    __half2 h23 = __floats2half2_rn((accA.z + accB.z) * wgt, (accA.w + accB.w) * wgt);
    uint2 pk = make_uint2(*(uint32_t*)&h01, *(uint32_t*)&h23);
    *(uint2*)&g_agg[(size_t)gw * FIN + lane * 4] = pk;
    __syncwarp();
    if (lane == 0) g_cur[gw] = 0;   // reset for next replay
}

// ---------------- single-pass fp16 HMMA GEMM (fused K=256) ----------------
// out = [feat | agg] @ [[W_self],[W_neigh]] + b
#define SM_TOTAL (128 * AS * 2)   // 34,816 bytes

__global__ void __launch_bounds__(256, 2) gemm_kernel(
    const float* __restrict__ feat,
    const float* __restrict__ bself,
    float* __restrict__ out)
{
    extern __shared__ char smem[];
    uint32_t sb = smem_u32(smem);
    const int t = threadIdx.x, w = t >> 5, lane = t & 31;
    const int rowBase = blockIdx.x * 128;
    const int wm = (w & 3) * 32, wc = w >> 2;

    float acc[2][8][4];
    #pragma unroll
    for (int mf = 0; mf < 2; mf++)
        #pragma unroll
        for (int nf = 0; nf < 8; nf++)
            #pragma unroll
            for (int e = 0; e < 4; e++) acc[mf][nf][e] = 0.f;

    const int fr = t >> 1, half = t & 1;
    const int gr = rowBase + fr;
    const bool valid = gr < NN;

    #pragma unroll
    for (int ph = 0; ph < 2; ph++) {
        if (ph) __syncthreads();   // protect smem reuse from previous phase

        if (ph == 0) {
            // ---- A fill: fp32 feat -> fp16 smem ----
            #pragma unroll 4
            for (int j = 0; j < 16; j++) {
                int c = half * 64 + j * 4;
                float4 v = valid ? *(const float4*)(feat + (size_t)gr * FIN + c)
                                 : make_float4(0.f, 0.f, 0.f, 0.f);
                __half2 h01 = __floats2half2_rn(v.x, v.y);
                __half2 h23 = __floats2half2_rn(v.z, v.w);
                uint32_t o = (uint32_t)((fr * AS + c) * 2);
                *(__half2*)(smem + o)     = h01;
                *(__half2*)(smem + o + 4) = h23;
            }
        } else {
            // ---- A fill: fp16 agg, straight 16B copies ----
            #pragma unroll
            for (int j = 0; j < 8; j++) {
                int c = half * 64 + j * 8;
                uint4 v = valid ? *(const uint4*)&g_agg[(size_t)gr * FIN + c]
                                : make_uint4(0u, 0u, 0u, 0u);
                *(uint4*)(smem + (uint32_t)((fr * AS + c) * 2)) = v;
            }
        }
        __syncthreads();

        // ---- MMA mainloop: 8 k-steps, double-buffered B fragments ----
        uint32_t bfr[2][16];
        {
            const uint4* hp = (const uint4*)&g_bf[ph][0][wc][lane][0];
            #pragma unroll
            for (int q = 0; q < 4; q++) *(uint4*)&bfr[0][q * 4] = hp[q];
        }
        #pragma unroll
        for (int ks = 0; ks < 8; ks++) {
            int cur = ks & 1, nxt = cur ^ 1;
            if (ks < 7) {
                const uint4* hp = (const uint4*)&g_bf[ph][ks + 1][wc][lane][0];
                #pragma unroll
                for (int q = 0; q < 4; q++) *(uint4*)&bfr[nxt][q * 4] = hp[q];
            }
            uint32_t afr[2][4];
            #pragma unroll
            for (int mf = 0; mf < 2; mf++)
                ldm_x4(afr[mf], ldm_addr(sb, wm + mf * 16, ks * 16, lane));
            #pragma unroll
            for (int mf = 0; mf < 2; mf++)
                #pragma unroll
                for (int nf = 0; nf < 8; nf++)
                    mma_fp16(acc[mf][nf], afr[mf], bfr[cur][nf * 2], bfr[cur][nf * 2 + 1]);
        }
    }

    // ---- epilogue: +bias, store ----
    const int wn = wc * 64, cg = (lane & 3) * 2, rr = lane >> 2;
    #pragma unroll
    for (int mf = 0; mf < 2; mf++) {
        int r0 = rowBase + wm + mf * 16 + rr, r1 = r0 + 8;
        #pragma unroll
        for (int nf = 0; nf < 8; nf++) {
            int col = wn + nf * 8 + cg;
            float b0 = __ldg(bself + col), b1 = __ldg(bself + col + 1);
            if (r0 < NN)
                *(float2*)(out + (size_t)r0 * FIN + col) =
                    make_float2(acc[mf][nf][0] + b0, acc[mf][nf][1] + b1);
            if (r1 < NN)
                *(float2*)(out + (size_t)r1 * FIN + col) =
                    make_float2(acc[mf][nf][2] + b0, acc[mf][nf][3] + b1);
        }
    }
}

// ---------------- launch ----------------
extern "C" void kernel_launch(void* const* d_in, const int* in_sizes, int n_in,
                              void* d_out, int out_size) {
    const float *feat = nullptr, *topkv = nullptr, *Wself = nullptr,
                *bself = nullptr, *Wneigh = nullptr;
    const int *topki = nullptr, *src = nullptr, *dst = nullptr;

    for (int i = 0; i < n_in; i++) {
        int s = in_sizes[i];
        const void* p = d_in[i];
        if (s == NN * FIN)       feat = (const float*)p;
        else if (s == NN * KK) { if (!topkv) topkv = (const float*)p; else topki = (const int*)p; }
        else if (s == EE)      { if (!src)   src   = (const int*)p;   else dst   = (const int*)p; }
        else if (s == 128*128) { if (!Wself) Wself = (const float*)p; else Wneigh = (const float*)p; }
        else if (s == 128)       bself = (const float*)p;
    }
    float* out = (float*)d_out;

    static int inited = 0;
    if (!inited) {
        cudaFuncSetAttribute(gemm_kernel, cudaFuncAttributeMaxDynamicSharedMemorySize, SM_TOTAL);
        inited = 1;
    }

    prep_kernel<<<SCAT_B + XS_B + WP_B, 256>>>(src, dst, topkv, topki, Wself, Wneigh);
    agg_kernel<<<(NN + 7) / 8, 256>>>();
    gemm_kernel<<<(NN + 127) / 128, 256, SM_TOTAL>>>(feat, bself, out);
}